// round 9
// baseline (speedup 1.0000x reference)
#include <cuda_runtime.h>
#include <cuda_fp16.h>
#include <cuda_bf16.h>

// Problem constants (fixed by the reference)
#define IN_N  (512 * 512)   // input pixels per batch
#define NB    64            // batch
#define NO    (512 * 512)   // outputs
#define NK    8             // connections per output

// Two half-transposed buffers: (N, 32) fp16 each = 16.75 MB (both L2-resident).
// Row n of each = 64B: batches b0..b0+31 for index n.
__device__ __align__(256) unsigned int g_xlo[(size_t)IN_N * 16];
__device__ __align__(256) unsigned int g_xhi[(size_t)IN_N * 16];

static __device__ __forceinline__ unsigned int h2bits(__half2 h) {
    return *reinterpret_cast<unsigned int*>(&h);
}

// ---------------------------------------------------------------------------
// Transpose half: (32 batches starting at b0, 64 n per block) f32 -> f16.
// Phase 1: lane (q=t&15 n-quad, bh=t>>4 batch-pair): two coalesced float4
//          loads, 4 packs, 4 STS (<=2-way conflict).
// smem layout: (row, bh) at (row>>1)*32 + (row&1)*16 + (( (bh>>2)^((row>>1)&3) )*4) + (bh&3)
// Phase 2: unit (nl=t>>2, g=t&3): one conflict-free LDS.128 + 512B/warp STG.128.
// ---------------------------------------------------------------------------
__global__ void __launch_bounds__(256) transpose_half_kernel(
    const float* __restrict__ in, unsigned int* __restrict__ xT, int b0)
{
    __shared__ __align__(16) unsigned int s[64 * 16];   // 4 KB
    const int n0 = blockIdx.x * 64;
    const int t  = threadIdx.x;

    // ---- Phase 1 ----
    {
        const int q  = t & 15;      // n-quad (n = n0 + 4q .. +3)
        const int bh = t >> 4;      // batch pair 0..15
        const float4* __restrict__ r0 =
            reinterpret_cast<const float4*>(in + (size_t)(b0 + 2 * bh) * IN_N);
        const float4* __restrict__ r1 =
            reinterpret_cast<const float4*>(in + (size_t)(b0 + 2 * bh + 1) * IN_N);
        const float4 a = r0[(n0 >> 2) + q];
        const float4 b = r1[(n0 >> 2) + q];
        const int chunk4 = bh >> 2;
        const int r2     = bh & 3;
        float av[4] = {a.x, a.y, a.z, a.w};
        float bv[4] = {b.x, b.y, b.z, b.w};
#pragma unroll
        for (int i = 0; i < 4; i++) {
            int row = 4 * q + i;
            int sw4 = chunk4 ^ ((row >> 1) & 3);
            s[(row >> 1) * 32 + (row & 1) * 16 + sw4 * 4 + r2] =
                h2bits(__floats2half2_rn(av[i], bv[i]));
        }
    }
    __syncthreads();

    // ---- Phase 2 ----
    {
        const int nl  = t >> 2;     // 0..63
        const int g   = t & 3;      // 16B chunk of the 64B row
        const int sw4 = g ^ ((nl >> 1) & 3);
        uint4 v = *reinterpret_cast<const uint4*>(
            &s[(nl >> 1) * 32 + (nl & 1) * 16 + sw4 * 4]);
        reinterpret_cast<uint4*>(xT)[(size_t)(n0 + nl) * 4 + g] = v;
    }
}

// ---------------------------------------------------------------------------
// Gather half: batches [b0, b0+32) from xT (N x 32 fp16 rows, 64B each).
// Block = 8 warps = 32 outputs (4 per warp). Lane: j=lane>>3 output,
// c=lane&7 chunk (4 batches, one uint2). HFMA2 accumulation in two depth-4
// chains (even/odd k), merged in fp32. Bitwise-identical math to R6/R7.
// ---------------------------------------------------------------------------
__global__ void __launch_bounds__(256) gather_half_kernel(
    const int*   __restrict__ conn,
    const float* __restrict__ w,
    float*       __restrict__ out,
    const uint2* __restrict__ xT,
    int b0)
{
    __shared__ float so[32][33];     // [batch_local][o_local]

    const int warp   = threadIdx.x >> 5;
    const int lane   = threadIdx.x & 31;
    const int o_base = blockIdx.x * 32;
    const int o_warp = o_base + warp * 4;
    const int j      = lane >> 3;    // output within warp's 4
    const int c      = lane & 7;     // 4-batch chunk

    const int   ci  = conn[(size_t)o_warp * NK + lane];
    const float wf  = w   [(size_t)o_warp * NK + lane];
    const int   wib = (int)__half_as_ushort(__float2half_rn(wf));

    __half2 accE[2], accO[2];
    accE[0] = __half2half2(__ushort_as_half((unsigned short)0));
    accE[1] = accE[0]; accO[0] = accE[0]; accO[1] = accE[0];

#pragma unroll
    for (int k = 0; k < NK; k++) {
        int src   = (lane & 24) + k;                    // lane j*8 + k
        int   idx = __shfl_sync(0xffffffffu, ci,  src);
        int   wb  = __shfl_sync(0xffffffffu, wib, src);
        __half2 wk2 = __half2half2(__ushort_as_half((unsigned short)wb));
        uint2 v = xT[(size_t)idx * 8 + c];              // 256B/warp over 4 rows
        __half2* acc = (k & 1) ? accO : accE;
        acc[0] = __hfma2(wk2, *reinterpret_cast<__half2*>(&v.x), acc[0]);
        acc[1] = __hfma2(wk2, *reinterpret_cast<__half2*>(&v.y), acc[1]);
    }

    // Merge chains in fp32; stage (conflict-free: bank = 4c + j + const)
#pragma unroll
    for (int m = 0; m < 2; m++) {
        float2 e = __half22float2(accE[m]);
        float2 o = __half22float2(accO[m]);
        so[c * 4 + 2 * m    ][warp * 4 + j] = e.x + o.x;
        so[c * 4 + 2 * m + 1][warp * 4 + j] = e.y + o.y;
    }
    __syncthreads();

    // Coalesced write-out: 32 batches x 32 outputs
    const int oc = threadIdx.x & 31;
    const int br = threadIdx.x >> 5;     // 0..7
#pragma unroll
    for (int ii = 0; ii < 4; ii++) {
        int b = br + 8 * ii;             // 0..31
        out[(size_t)(b0 + b) * NO + o_base + oc] = so[b][oc];
    }
}

extern "C" void kernel_launch(void* const* d_in, const int* in_sizes, int n_in,
                              void* d_out, int out_size) {
    const float* input = (const float*)d_in[0];   // (64, 512, 512) f32
    const int*   conn  = (const int*)  d_in[1];   // (O, 8) i32
    const float* wts   = (const float*)d_in[2];   // (O, 8) f32
    float*       out   = (float*)d_out;           // (64, O) f32

    unsigned int* xlo; cudaGetSymbolAddress((void**)&xlo, g_xlo);
    unsigned int* xhi; cudaGetSymbolAddress((void**)&xhi, g_xhi);

    // One-time stream/event setup (runs on the uncaptured correctness call;
    // identical captured work on every subsequent call).
    static cudaStream_t s2  = nullptr;
    static cudaEvent_t  evA = nullptr, evB = nullptr;
    static int          init_state = 0;   // 0 = not tried, 1 = ok, -1 = failed
    if (init_state == 0) {
        bool ok = (cudaStreamCreateWithFlags(&s2, cudaStreamNonBlocking) == cudaSuccess) &&
                  (cudaEventCreateWithFlags(&evA, cudaEventDisableTiming) == cudaSuccess) &&
                  (cudaEventCreateWithFlags(&evB, cudaEventDisableTiming) == cudaSuccess);
        init_state = ok ? 1 : -1;
    }

    if (init_state == 1) {
        // T1 on default stream
        transpose_half_kernel<<<IN_N / 64, 256>>>(input, xlo, 0);
        // Fork: T2 on s2 (waits for nothing but stream order via event on T1's
        // completion is NOT needed — T2 only reads input and writes xhi, fully
        // independent of T1. Fork from the capture origin point.)
        cudaEventRecord(evA, 0);
        cudaStreamWaitEvent(s2, evA, 0);
        transpose_half_kernel<<<IN_N / 64, 256, 0, s2>>>(input, xhi, 32);
        // G1 on default stream (after T1, stream-ordered)
        gather_half_kernel<<<NO / 32, 256>>>(conn, wts, out, (const uint2*)xlo, 0);
        // Join: G2 needs T2 complete
        cudaEventRecord(evB, s2);
        cudaStreamWaitEvent(0, evB, 0);
        gather_half_kernel<<<NO / 32, 256>>>(conn, wts, out, (const uint2*)xhi, 32);
    } else {
        // Sequential fallback (same math, same outputs)
        transpose_half_kernel<<<IN_N / 64, 256>>>(input, xlo, 0);
        transpose_half_kernel<<<IN_N / 64, 256>>>(input, xhi, 32);
        gather_half_kernel<<<NO / 32, 256>>>(conn, wts, out, (const uint2*)xlo, 0);
        gather_half_kernel<<<NO / 32, 256>>>(conn, wts, out, (const uint2*)xhi, 32);
    }
}

// round 10
// speedup vs baseline: 1.0076x; 1.0076x over previous
#include <cuda_runtime.h>
#include <cuda_fp16.h>
#include <cuda_bf16.h>

// Problem constants (fixed by the reference)
#define IN_N  (512 * 512)   // input pixels per batch
#define NB    64            // batch
#define NO    (512 * 512)   // outputs
#define NK    8             // connections per output

// Two half-transposed buffers: (N, 32) fp16 each = 16.75 MB (both L2-resident).
// Row n = 64B: batches b0..b0+31 for index n.
__device__ __align__(256) unsigned int g_xlo[(size_t)IN_N * 16];
__device__ __align__(256) unsigned int g_xhi[(size_t)IN_N * 16];

static __device__ __forceinline__ unsigned int h2bits(__half2 h) {
    return *reinterpret_cast<unsigned int*>(&h);
}
static __device__ __forceinline__ __half2 bits2h(unsigned int u) {
    return *reinterpret_cast<__half2*>(&u);
}

// ---------------------------------------------------------------------------
// Transpose half: (32 batches starting at b0) f32 -> (N,32) f16. (R8, 7.5us)
// ---------------------------------------------------------------------------
__global__ void __launch_bounds__(256) transpose_half_kernel(
    const float* __restrict__ in, unsigned int* __restrict__ xT, int b0)
{
    __shared__ __align__(16) unsigned int s[64 * 16];   // 4 KB
    const int n0 = blockIdx.x * 64;
    const int t  = threadIdx.x;

    {
        const int q  = t & 15;      // n-quad (n = n0 + 4q .. +3)
        const int bh = t >> 4;      // batch pair 0..15
        const float4* __restrict__ r0 =
            reinterpret_cast<const float4*>(in + (size_t)(b0 + 2 * bh) * IN_N);
        const float4* __restrict__ r1 =
            reinterpret_cast<const float4*>(in + (size_t)(b0 + 2 * bh + 1) * IN_N);
        const float4 a = r0[(n0 >> 2) + q];
        const float4 b = r1[(n0 >> 2) + q];
        const int chunk4 = bh >> 2;
        const int r2     = bh & 3;
        float av[4] = {a.x, a.y, a.z, a.w};
        float bv[4] = {b.x, b.y, b.z, b.w};
#pragma unroll
        for (int i = 0; i < 4; i++) {
            int row = 4 * q + i;
            int sw4 = chunk4 ^ ((row >> 1) & 3);
            s[(row >> 1) * 32 + (row & 1) * 16 + sw4 * 4 + r2] =
                h2bits(__floats2half2_rn(av[i], bv[i]));
        }
    }
    __syncthreads();
    {
        const int nl  = t >> 2;     // 0..63
        const int g   = t & 3;      // 16B chunk of the 64B row
        const int sw4 = g ^ ((nl >> 1) & 3);
        uint4 v = *reinterpret_cast<const uint4*>(
            &s[(nl >> 1) * 32 + (nl & 1) * 16 + sw4 * 4]);
        reinterpret_cast<uint4*>(xT)[(size_t)(n0 + nl) * 4 + g] = v;
    }
}

// ---------------------------------------------------------------------------
// Gather half: batches [b0, b0+32). 64B rows -> one LDG.128 (512B/warp)
// spans 8 OUTPUT rows. Block = 8 warps = 64 outputs.
// Lane: j = lane>>2 (output within warp's 8), c = lane&3 (8-batch chunk).
// HFMA2 accumulation, even/odd-k chains merged in fp32 (bitwise == R8).
// ---------------------------------------------------------------------------
__global__ void __launch_bounds__(256) gather_half_kernel(
    const int*   __restrict__ conn,
    const float* __restrict__ w,
    float*       __restrict__ out,
    const uint4* __restrict__ xT,
    int b0)
{
    __shared__ float so[32][65];     // [batch_local][o_local(64)]

    const int warp   = threadIdx.x >> 5;
    const int lane   = threadIdx.x & 31;
    const int o_base = blockIdx.x * 64;
    const int o_warp = o_base + warp * 8;     // warp's 8 outputs
    const int j      = lane >> 2;             // output 0..7
    const int c      = lane & 3;              // chunk 0..3 (8 batches)

    // Warp's 8 conn/weight rows = 64 values: two coalesced loads each.
    const int   ci0 = conn[(size_t)o_warp * NK + lane];        // rows 0..3
    const int   ci1 = conn[(size_t)o_warp * NK + 32 + lane];   // rows 4..7
    const int   wb0 = (int)__half_as_ushort(__float2half_rn(w[(size_t)o_warp * NK + lane]));
    const int   wb1 = (int)__half_as_ushort(__float2half_rn(w[(size_t)o_warp * NK + 32 + lane]));

    __half2 accE[4], accO[4];
    {
        __half2 z = __half2half2(__ushort_as_half((unsigned short)0));
#pragma unroll
        for (int m = 0; m < 4; m++) { accE[m] = z; accO[m] = z; }
    }

    const int slo = (j & 3) * 8;
#pragma unroll
    for (int k = 0; k < NK; k++) {
        int s   = slo + k;
        int ia  = __shfl_sync(0xffffffffu, ci0, s);
        int ib  = __shfl_sync(0xffffffffu, ci1, s);
        int wa  = __shfl_sync(0xffffffffu, wb0, s);
        int wbx = __shfl_sync(0xffffffffu, wb1, s);
        int idx = (j < 4) ? ia : ib;
        int wb_ = (j < 4) ? wa : wbx;
        __half2 wk2 = __half2half2(__ushort_as_half((unsigned short)wb_));
        uint4 v = xT[(size_t)idx * 4 + c];    // 512B/warp over 8 rows
        __half2* acc = (k & 1) ? accO : accE;
        acc[0] = __hfma2(wk2, bits2h(v.x), acc[0]);
        acc[1] = __hfma2(wk2, bits2h(v.y), acc[1]);
        acc[2] = __hfma2(wk2, bits2h(v.z), acc[2]);
        acc[3] = __hfma2(wk2, bits2h(v.w), acc[3]);
    }

    // Merge chains in fp32; stage. Banks: (c*8)*65 + warp*8 + j -> c*8+j mod32,
    // all 32 distinct per warp: conflict-free.
#pragma unroll
    for (int m = 0; m < 4; m++) {
        float2 e = __half22float2(accE[m]);
        float2 o = __half22float2(accO[m]);
        so[c * 8 + 2 * m    ][warp * 8 + j] = e.x + o.x;
        so[c * 8 + 2 * m + 1][warp * 8 + j] = e.y + o.y;
    }
    __syncthreads();

    // Coalesced write-out: 32 batches x 64 outputs.
    const int oc = threadIdx.x & 63;
    const int r0 = threadIdx.x >> 6;          // 0..3
#pragma unroll
    for (int i = 0; i < 8; i++) {
        int b = r0 + 4 * i;                   // 0..31
        out[(size_t)(b0 + b) * NO + o_base + oc] = so[b][oc];
    }
}

extern "C" void kernel_launch(void* const* d_in, const int* in_sizes, int n_in,
                              void* d_out, int out_size) {
    const float* input = (const float*)d_in[0];   // (64, 512, 512) f32
    const int*   conn  = (const int*)  d_in[1];   // (O, 8) i32
    const float* wts   = (const float*)d_in[2];   // (O, 8) f32
    float*       out   = (float*)d_out;           // (64, O) f32

    unsigned int* xlo; cudaGetSymbolAddress((void**)&xlo, g_xlo);
    unsigned int* xhi; cudaGetSymbolAddress((void**)&xhi, g_xhi);

    // One-time stream/event setup (first call is the uncaptured correctness
    // run; captured calls replay the identical DAG).
    static cudaStream_t sA = nullptr, sB = nullptr;
    static cudaEvent_t  evStart = nullptr, evT1 = nullptr,
                        evEndA = nullptr, evEndB = nullptr;
    static int init_state = 0;
    if (init_state == 0) {
        bool ok =
            (cudaStreamCreateWithFlags(&sA, cudaStreamNonBlocking) == cudaSuccess) &&
            (cudaStreamCreateWithFlags(&sB, cudaStreamNonBlocking) == cudaSuccess) &&
            (cudaEventCreateWithFlags(&evStart, cudaEventDisableTiming) == cudaSuccess) &&
            (cudaEventCreateWithFlags(&evT1,    cudaEventDisableTiming) == cudaSuccess) &&
            (cudaEventCreateWithFlags(&evEndA,  cudaEventDisableTiming) == cudaSuccess) &&
            (cudaEventCreateWithFlags(&evEndB,  cudaEventDisableTiming) == cudaSuccess);
        init_state = ok ? 1 : -1;
    }

    if (init_state == 1) {
        // Fork both worker streams from the capture-origin stream.
        cudaEventRecord(evStart, 0);
        cudaStreamWaitEvent(sA, evStart, 0);
        cudaStreamWaitEvent(sB, evStart, 0);

        // Chain A: T1 -> G1
        transpose_half_kernel<<<IN_N / 64, 256, 0, sA>>>(input, xlo, 0);
        cudaEventRecord(evT1, sA);
        gather_half_kernel<<<NO / 64, 256, 0, sA>>>(conn, wts, out,
                                                    (const uint4*)xlo, 0);
        // Chain B (staggered): T2 after T1, then G2 — T2 runs under G1.
        cudaStreamWaitEvent(sB, evT1, 0);
        transpose_half_kernel<<<IN_N / 64, 256, 0, sB>>>(input, xhi, 32);
        gather_half_kernel<<<NO / 64, 256, 0, sB>>>(conn, wts, out,
                                                    (const uint4*)xhi, 32);

        // Join both chains back to the capture stream.
        cudaEventRecord(evEndA, sA);
        cudaEventRecord(evEndB, sB);
        cudaStreamWaitEvent(0, evEndA, 0);
        cudaStreamWaitEvent(0, evEndB, 0);
    } else {
        // Sequential fallback (identical math and outputs)
        transpose_half_kernel<<<IN_N / 64, 256>>>(input, xlo, 0);
        transpose_half_kernel<<<IN_N / 64, 256>>>(input, xhi, 32);
        gather_half_kernel<<<NO / 64, 256>>>(conn, wts, out, (const uint4*)xlo, 0);
        gather_half_kernel<<<NO / 64, 256>>>(conn, wts, out, (const uint4*)xhi, 32);
    }
}

// round 11
// speedup vs baseline: 1.0281x; 1.0204x over previous
#include <cuda_runtime.h>
#include <cuda_fp16.h>
#include <cuda_bf16.h>

// Problem constants (fixed by the reference)
#define IN_N  (512 * 512)   // input pixels per batch
#define NB    64            // batch
#define NO    (512 * 512)   // outputs
#define NK    8             // connections per output

// Two half-transposed buffers: (N, 32) fp16 each = 16.75 MB (L2-resident).
// Row n = 64B: batches b0..b0+31 for index n.
__device__ __align__(256) unsigned int g_xlo[(size_t)IN_N * 16];
__device__ __align__(256) unsigned int g_xhi[(size_t)IN_N * 16];

static __device__ __forceinline__ unsigned int h2bits(__half2 h) {
    return *reinterpret_cast<unsigned int*>(&h);
}
static __device__ __forceinline__ __half2 bits2h(unsigned int u) {
    return *reinterpret_cast<__half2*>(&u);
}

// ---------------------------------------------------------------------------
// Transpose one 64-n tile of 32 batches (b0..b0+31) f32 -> (N,32) f16.
// (Bit-identical data path to R9's transpose_half_kernel.)
// s: 1024 uints (4 KB) of scratch smem.
// ---------------------------------------------------------------------------
static __device__ __forceinline__ void transpose_tile(
    const float* __restrict__ in, unsigned int* __restrict__ xT,
    int b0, int n0, unsigned int* s)
{
    const int t = threadIdx.x;
    {
        const int q  = t & 15;      // n-quad (n = n0 + 4q .. +3)
        const int bh = t >> 4;      // batch pair 0..15
        const float4* __restrict__ r0 =
            reinterpret_cast<const float4*>(in + (size_t)(b0 + 2 * bh) * IN_N);
        const float4* __restrict__ r1 =
            reinterpret_cast<const float4*>(in + (size_t)(b0 + 2 * bh + 1) * IN_N);
        const float4 a = r0[(n0 >> 2) + q];
        const float4 b = r1[(n0 >> 2) + q];
        const int chunk4 = bh >> 2;
        const int r2     = bh & 3;
        float av[4] = {a.x, a.y, a.z, a.w};
        float bv[4] = {b.x, b.y, b.z, b.w};
#pragma unroll
        for (int i = 0; i < 4; i++) {
            int row = 4 * q + i;
            int sw4 = chunk4 ^ ((row >> 1) & 3);
            s[(row >> 1) * 32 + (row & 1) * 16 + sw4 * 4 + r2] =
                h2bits(__floats2half2_rn(av[i], bv[i]));
        }
    }
    __syncthreads();
    {
        const int nl  = t >> 2;     // 0..63
        const int g   = t & 3;      // 16B chunk of the 64B row
        const int sw4 = g ^ ((nl >> 1) & 3);
        uint4 v = *reinterpret_cast<const uint4*>(
            &s[(nl >> 1) * 32 + (nl & 1) * 16 + sw4 * 4]);
        reinterpret_cast<uint4*>(xT)[(size_t)(n0 + nl) * 4 + g] = v;
    }
}

// ---------------------------------------------------------------------------
// Gather one 64-output tile for batches [b0, b0+32) from xT (64B rows).
// smem (idx,w) table in K-MAJOR layout: tbl[k*64 + o_local] = {idx, wbits}.
//   - main-loop LDS.64 at fixed k: 8 distinct addrs/warp, 4-way broadcast,
//     conflict-free.
// Lane: j = lane>>2 (output within warp's 8), c = lane&3 (8-batch chunk).
// HFMA2 even/odd-k chains merged in fp32 (bitwise == R8/R9 math).
// tbl: 512 uint2 (4 KB); so: float[32][65] (8.32 KB).
// ---------------------------------------------------------------------------
static __device__ __forceinline__ void gather_tile(
    const int*   __restrict__ conn,
    const float* __restrict__ w,
    float*       __restrict__ out,
    const uint4* __restrict__ xT,
    int b0, int o_base,
    uint2* tbl, float (*so)[65])
{
    const int t = threadIdx.x;

    // Prologue: coalesced conn/w loads -> k-major (idx, wbits) table.
    {
        const uint2*  c2 = reinterpret_cast<const uint2*>(conn + (size_t)o_base * NK);
        const float2* w2 = reinterpret_cast<const float2*>(w    + (size_t)o_base * NK);
        uint2  ci = c2[t];
        float2 wf = w2[t];
        int o  = t >> 2;            // 0..63
        int k0 = (t & 3) * 2;       // 0,2,4,6
        unsigned int wa = (unsigned int)__half_as_ushort(__float2half_rn(wf.x));
        unsigned int wb = (unsigned int)__half_as_ushort(__float2half_rn(wf.y));
        tbl[k0 * 64 + o]       = make_uint2(ci.x, wa);
        tbl[(k0 + 1) * 64 + o] = make_uint2(ci.y, wb);
    }
    __syncthreads();

    const int warp = t >> 5;
    const int lane = t & 31;
    const int j    = lane >> 2;     // output 0..7 within warp
    const int c    = lane & 3;      // 8-batch chunk
    const int ol   = warp * 8 + j;  // output local 0..63

    __half2 accE[4], accO[4];
    {
        __half2 z = __half2half2(__ushort_as_half((unsigned short)0));
#pragma unroll
        for (int m = 0; m < 4; m++) { accE[m] = z; accO[m] = z; }
    }

#pragma unroll
    for (int k = 0; k < NK; k++) {
        uint2 e = tbl[k * 64 + ol];                 // conflict-free broadcast
        __half2 wk2 = __half2half2(__ushort_as_half((unsigned short)e.y));
        uint4 v = xT[(size_t)e.x * 4 + c];          // 512B/warp over 8 rows
        __half2* acc = (k & 1) ? accO : accE;
        acc[0] = __hfma2(wk2, bits2h(v.x), acc[0]);
        acc[1] = __hfma2(wk2, bits2h(v.y), acc[1]);
        acc[2] = __hfma2(wk2, bits2h(v.z), acc[2]);
        acc[3] = __hfma2(wk2, bits2h(v.w), acc[3]);
    }

    // Merge chains in fp32; stage (bank = c*8 + j + const: conflict-free).
#pragma unroll
    for (int m = 0; m < 4; m++) {
        float2 e = __half22float2(accE[m]);
        float2 o = __half22float2(accO[m]);
        so[c * 8 + 2 * m    ][ol] = e.x + o.x;
        so[c * 8 + 2 * m + 1][ol] = e.y + o.y;
    }
    __syncthreads();

    // Coalesced write-out: 32 batches x 64 outputs.
    const int oc = t & 63;
    const int r0 = t >> 6;          // 0..3
#pragma unroll
    for (int i = 0; i < 8; i++) {
        int b = r0 + 4 * i;         // 0..31
        out[(size_t)(b0 + b) * NO + o_base + oc] = so[b][oc];
    }
}

// ---------------------------------------------------------------------------
// K1: transpose LO half (batches 0..31), grid = 4096.
// ---------------------------------------------------------------------------
__global__ void __launch_bounds__(256) t_lo_kernel(const float* __restrict__ in) {
    __shared__ __align__(16) unsigned int s[64 * 16];
    transpose_tile(in, g_xlo, 0, blockIdx.x * 64, s);
}

// ---------------------------------------------------------------------------
// K2: fused co-scheduled kernel, grid = 8192.
// Even blocks: transpose HI tile (bid>>1). Odd blocks: gather LO tile (bid>>1).
// Interleaving by blockIdx keeps both roles co-resident on the SMs, so the
// DRAM-bound transpose hides under the LTS-bound gather.
// ---------------------------------------------------------------------------
__global__ void __launch_bounds__(256, 8) fused_thi_glo_kernel(
    const float* __restrict__ in,
    const int*   __restrict__ conn,
    const float* __restrict__ w,
    float*       __restrict__ out)
{
    __shared__ __align__(16) unsigned char smem_raw[4096 + 32 * 65 * 4];
    const int bid  = blockIdx.x;
    const int tile = bid >> 1;
    if ((bid & 1) == 0) {
        transpose_tile(in, g_xhi, 32, tile * 64,
                       reinterpret_cast<unsigned int*>(smem_raw));
    } else {
        gather_tile(conn, w, out, reinterpret_cast<const uint4*>(g_xlo),
                    0, tile * 64,
                    reinterpret_cast<uint2*>(smem_raw),
                    reinterpret_cast<float(*)[65]>(smem_raw + 4096));
    }
}

// ---------------------------------------------------------------------------
// K3: gather HI half (batches 32..63), grid = 4096.
// ---------------------------------------------------------------------------
__global__ void __launch_bounds__(256, 8) g_hi_kernel(
    const int*   __restrict__ conn,
    const float* __restrict__ w,
    float*       __restrict__ out)
{
    __shared__ __align__(16) unsigned char smem_raw[4096 + 32 * 65 * 4];
    gather_tile(conn, w, out, reinterpret_cast<const uint4*>(g_xhi),
                32, blockIdx.x * 64,
                reinterpret_cast<uint2*>(smem_raw),
                reinterpret_cast<float(*)[65]>(smem_raw + 4096));
}

extern "C" void kernel_launch(void* const* d_in, const int* in_sizes, int n_in,
                              void* d_out, int out_size) {
    const float* input = (const float*)d_in[0];   // (64, 512, 512) f32
    const int*   conn  = (const int*)  d_in[1];   // (O, 8) i32
    const float* wts   = (const float*)d_in[2];   // (O, 8) f32
    float*       out   = (float*)d_out;           // (64, O) f32

    t_lo_kernel       <<<IN_N / 64,     256>>>(input);
    fused_thi_glo_kernel<<<2 * (NO / 64), 256>>>(input, conn, wts, out);
    g_hi_kernel       <<<NO / 64,      256>>>(conn, wts, out);
}

// round 12
// speedup vs baseline: 1.2554x; 1.2211x over previous
#include <cuda_runtime.h>
#include <cuda_fp16.h>
#include <cuda_bf16.h>

// Problem constants (fixed by the reference)
#define IN_N  (512 * 512)   // input pixels per batch
#define NB    64            // batch
#define NO    (512 * 512)   // outputs
#define NK    8             // connections per output

// Scratch: input transposed to (N, B) in fp16: each index row is a contiguous
// 128B run of all 64 batch values (33.5 MB, L2-resident).
__device__ __align__(256) __half g_xTh[(size_t)IN_N * NB];

static __device__ __forceinline__ unsigned int h2bits(__half2 h) {
    return *reinterpret_cast<unsigned int*>(&h);
}

// ---------------------------------------------------------------------------
// Kernel 1: transpose (B, N) f32 -> (N, B) f16, high-MLP version.
// Tile: 128 n x 64 b per block (2048 blocks). Each thread front-batches
// 8 independent LDG.128 (MLP_p1 = 8) to hide DRAM latency (the R10 profile
// showed the transpose is latency-bound, not bandwidth-bound).
//
// smem: s[128][32] uints (16 KB). (row, bh) stored at
//   s[row*32 + ((bh>>2) ^ ((row>>2)&7))*4 + (bh&3)]
// Phase 2: unit (nl, g 0..7): LDS.128 at chunk g^((nl>>2)&7) — per 8-lane
// phase all 8 sw values distinct -> conflict-free; STG 512B/warp contiguous.
// Resulting g_xTh layout is bit-identical to R7's.
// ---------------------------------------------------------------------------
__global__ void __launch_bounds__(256) transpose_kernel(const float* __restrict__ in) {
    __shared__ __align__(16) unsigned int s[128 * 32];   // 16 KB
    const int n0 = blockIdx.x * 128;
    const int t  = threadIdx.x;

    // ---- Phase 1: 8 front-batched float4 loads, then convert + STS ----
    const int q0 = t & 15;        // base n-quad
    const int b0 = t >> 4;        // base batch-pair (0..15)

    float4 A[2][2], B[2][2];      // [i: bh half][j: q half]
#pragma unroll
    for (int i = 0; i < 2; i++) {
        const int bh = b0 + 16 * i;               // 0..31
        const float4* __restrict__ r0 =
            reinterpret_cast<const float4*>(in + (size_t)(2 * bh) * IN_N);
        const float4* __restrict__ r1 =
            reinterpret_cast<const float4*>(in + (size_t)(2 * bh + 1) * IN_N);
#pragma unroll
        for (int jq = 0; jq < 2; jq++) {
            const int q = q0 + 16 * jq;           // 0..31
            A[i][jq] = r0[(n0 >> 2) + q];
            B[i][jq] = r1[(n0 >> 2) + q];
        }
    }

#pragma unroll
    for (int i = 0; i < 2; i++) {
        const int bh    = b0 + 16 * i;
        const int chunk = bh >> 2;                // 0..7
        const int r2    = bh & 3;
#pragma unroll
        for (int jq = 0; jq < 2; jq++) {
            const int q = q0 + 16 * jq;           // row>>2 == q
            float av[4] = {A[i][jq].x, A[i][jq].y, A[i][jq].z, A[i][jq].w};
            float bv[4] = {B[i][jq].x, B[i][jq].y, B[i][jq].z, B[i][jq].w};
            const int sw = chunk ^ (q & 7);
#pragma unroll
            for (int e = 0; e < 4; e++) {
                int row = 4 * q + e;              // 0..127
                s[row * 32 + sw * 4 + r2] =
                    h2bits(__floats2half2_rn(av[e], bv[e]));
            }
        }
    }
    __syncthreads();

    // ---- Phase 2: LDS.128 + contiguous STG.128 ----
    uint4* __restrict__ xT4 = reinterpret_cast<uint4*>(g_xTh);
#pragma unroll
    for (int i1 = 0; i1 < 4; i1++) {
        int u  = t + 256 * i1;                    // 0..1023
        int nl = u >> 3;                          // 0..127
        int g  = u & 7;                           // 16B chunk of 128B row
        int sw = g ^ ((nl >> 2) & 7);
        uint4 v = *reinterpret_cast<const uint4*>(&s[nl * 32 + sw * 4]);
        xT4[(size_t)(n0 + nl) * 8 + g] = v;       // 512B/warp contiguous
    }
}

// ---------------------------------------------------------------------------
// Kernel 2: gather + weighted reduce with packed HFMA2 accumulation.
// (EXACT R7 kernel — measured 30.4us at ~94% of the LTS byte cap with
//  compulsory-only DRAM; bytes irreducible at fp16. Do not touch.)
// ---------------------------------------------------------------------------
__global__ void __launch_bounds__(256) sparse_linear_kernel(
    const int*   __restrict__ conn,
    const float* __restrict__ w,
    float*       __restrict__ out)
{
    __shared__ float so[64][33];     // [batch][o_local], pitch 33

    const int warp   = threadIdx.x >> 5;
    const int lane   = threadIdx.x & 31;
    const int o_base = blockIdx.x * 32;
    const int o_warp = o_base + warp * 4;
    const int j      = lane >> 3;    // output within warp's 4
    const int c      = lane & 7;     // batch chunk (8 batches)

    // Coalesced: warp's 4 conn/weight rows (4 x 8 = 32 elems)
    const int   ci  = conn[(size_t)o_warp * NK + lane];
    const float wf  = w   [(size_t)o_warp * NK + lane];
    const int   wib = (int)__half_as_ushort(__float2half_rn(wf));

    const uint4* __restrict__ xT4 = reinterpret_cast<const uint4*>(g_xTh);

    __half2 accE[4], accO[4];        // even-k / odd-k chains (depth 4 each)
#pragma unroll
    for (int m = 0; m < 4; m++) {
        accE[m] = __half2half2(__ushort_as_half((unsigned short)0));
        accO[m] = accE[m];
    }

#pragma unroll
    for (int k = 0; k < NK; k++) {
        int src   = (lane & 24) + k;                    // lane j*8 + k
        int   idx = __shfl_sync(0xffffffffu, ci,  src);
        int   wb  = __shfl_sync(0xffffffffu, wib, src);
        __half2 wk2 = __half2half2(__ushort_as_half((unsigned short)wb));
        uint4 v = xT4[(size_t)idx * 8 + c];             // 512B/warp: 4 rows
        __half2* acc = (k & 1) ? accO : accE;
        acc[0] = __hfma2(wk2, *reinterpret_cast<__half2*>(&v.x), acc[0]);
        acc[1] = __hfma2(wk2, *reinterpret_cast<__half2*>(&v.y), acc[1]);
        acc[2] = __hfma2(wk2, *reinterpret_cast<__half2*>(&v.z), acc[2]);
        acc[3] = __hfma2(wk2, *reinterpret_cast<__half2*>(&v.w), acc[3]);
    }

    // Epilogue: merge chains in fp32, stage to smem.
#pragma unroll
    for (int m = 0; m < 4; m++) {
        float2 e = __half22float2(accE[m]);
        float2 o = __half22float2(accO[m]);
        so[c * 8 + 2 * m    ][warp * 4 + j] = e.x + o.x;
        so[c * 8 + 2 * m + 1][warp * 4 + j] = e.y + o.y;
    }
    __syncthreads();

    // Coalesced write-out: lane oc -> output column, 8 batch rows per thread
    const int oc = threadIdx.x & 31;
    const int br = threadIdx.x >> 5;
#pragma unroll
    for (int i = 0; i < 8; i++) {
        int b = br * 8 + i;
        out[(size_t)b * NO + o_base + oc] = so[b][oc];  // conflict-free LDS
    }
}

extern "C" void kernel_launch(void* const* d_in, const int* in_sizes, int n_in,
                              void* d_out, int out_size) {
    const float* input = (const float*)d_in[0];   // (64, 512, 512) f32
    const int*   conn  = (const int*)  d_in[1];   // (O, 8) i32
    const float* wts   = (const float*)d_in[2];   // (O, 8) f32
    float*       out   = (float*)d_out;           // (64, O) f32

    transpose_kernel<<<IN_N / 128, 256>>>(input);
    sparse_linear_kernel<<<NO / 32, 256>>>(conn, wts, out);
}